// round 5
// baseline (speedup 1.0000x reference)
#include <cuda_runtime.h>
#include <math.h>

#define NN 10000
#define EE 320000
#define PI_F 3.14159265358979323846f
#define CDIV(a,b) (((a)+(b)-1)/(b))

// ---------------- scratch (static device memory; no allocations) ----------------
__device__ float g_h [NN*128];
__device__ float g_C1[NN*128];
__device__ float g_S1[NN*384];
__device__ float g_Y [NN*384];
__device__ float g_X2[NN*256];
__device__ float g_C2[NN*256];
__device__ float g_S2[NN*768];
__device__ float g_Z [NN*768];
__device__ float g_X3[NN*512];
__device__ float g_C3[NN*512];
__device__ float g_S3[NN*512];
__device__ float g_Wo[NN*512];
__device__ float g_rep[NN*896];
__device__ float g_agg[NN*896];
__device__ float g_filt[3*NN];
__device__ int   g_src[EE];
__device__ int   g_dst[EE];
__device__ int   g_is64;
__device__ int   g_deg[NN];
__device__ int   g_off[NN+1];
__device__ int   g_cur[NN];
__device__ int   g_esrc[EE];
__device__ float g_hgat[NN*32];
__device__ float g_asrc[NN*2];
__device__ float g_adst[NN*2];
__device__ float g_gatout[NN*32];
__device__ float g_gv[NN*16];
__device__ float g_o2[NN*16];

// ---------------- edge_index dtype detection + conversion ----------------
// Reference builds edge_index as int32 then .astype(int64); with JAX x64
// disabled that astype is a no-op, so the buffer is most likely int32.
// Detect at runtime: int64 little-endian non-negative values < 2^31 have all
// high 32-bit words == 0. OR the odd words of the first 4096 entries.
__global__ void k_detect(const unsigned int* __restrict__ w) {
    __shared__ unsigned acc_s;
    if (threadIdx.x == 0) acc_s = 0u;
    __syncthreads();
    unsigned a = 0u;
    for (int i = threadIdx.x; i < 4096; i += blockDim.x)
        a |= w[2*i + 1];
    atomicOr(&acc_s, a);
    __syncthreads();
    if (threadIdx.x == 0) g_is64 = (acc_s == 0u) ? 1 : 0;
}

__global__ void k_conv(const void* __restrict__ ei) {
    int e = blockIdx.x*256 + threadIdx.x;
    if (e >= EE) return;
    if (g_is64) {
        const long long* p = (const long long*)ei;
        g_src[e] = (int)p[e];
        g_dst[e] = (int)p[EE + e];
    } else {
        const int* p = (const int*)ei;
        g_src[e] = p[e];
        g_dst[e] = p[EE + e];
    }
}

// ---------------- SGEMM: C = op(A) @ B,  A = V (NN x NN), 128x128x8 tiles ----------------
template<bool TRANSA>
__global__ void __launch_bounds__(256,2) sgemm_k(
    const float* __restrict__ A, const float* __restrict__ B, float* __restrict__ C,
    int M, int K, int NC, int itersPerSplit)
{
    __shared__ float As[8][128];
    __shared__ float Bs[8][128];
    const int tid = threadIdx.x;
    const int bm = blockIdx.x * 128;
    const int bn = blockIdx.y * 128;
    const int tx = tid & 15, ty = tid >> 4;

    const int totalIters = K >> 3;
    int it0 = blockIdx.z * itersPerSplit;
    int it1 = it0 + itersPerSplit; if (it1 > totalIters) it1 = totalIters;

    float acc[8][8];
#pragma unroll
    for (int r = 0; r < 8; r++)
#pragma unroll
        for (int c = 0; c < 8; c++) acc[r][c] = 0.f;

    const int a_row = tid >> 1, a_half = tid & 1;
    const int t_kk  = tid >> 5;
    const int t_m4  = (tid & 31) << 2;
    const int b_r   = tid >> 5, b_c4 = (tid & 31) << 2;

    for (int it = it0; it < it1; ++it) {
        const int k0 = it << 3;
        float4 av = make_float4(0.f,0.f,0.f,0.f);
        if (TRANSA) {
            int gc = bm + t_m4;
            if (gc < M) av = *(const float4*)&A[(size_t)(k0 + t_kk) * M + gc];
        } else {
            int gr = bm + a_row;
            if (gr < M) av = *(const float4*)&A[(size_t)gr * K + k0 + (a_half<<2)];
        }
        float4 bv = *(const float4*)&B[(size_t)(k0 + b_r) * NC + bn + b_c4];
        __syncthreads();
        if (TRANSA) {
            *(float4*)&As[t_kk][t_m4] = av;
        } else {
            As[(a_half<<2)+0][a_row] = av.x;
            As[(a_half<<2)+1][a_row] = av.y;
            As[(a_half<<2)+2][a_row] = av.z;
            As[(a_half<<2)+3][a_row] = av.w;
        }
        *(float4*)&Bs[b_r][b_c4] = bv;
        __syncthreads();
#pragma unroll
        for (int k = 0; k < 8; k++) {
            float a[8], b[8];
            *(float4*)&a[0] = *(float4*)&As[k][(ty<<2)];
            *(float4*)&a[4] = *(float4*)&As[k][64 + (ty<<2)];
            *(float4*)&b[0] = *(float4*)&Bs[k][(tx<<2)];
            *(float4*)&b[4] = *(float4*)&Bs[k][64 + (tx<<2)];
#pragma unroll
            for (int r = 0; r < 8; r++)
#pragma unroll
                for (int c = 0; c < 8; c++)
                    acc[r][c] += a[r] * b[c];
        }
    }

    const bool split = (gridDim.z > 1);
#pragma unroll
    for (int rh = 0; rh < 2; rh++) {
#pragma unroll
        for (int r = 0; r < 4; r++) {
            int row = bm + rh*64 + (ty<<2) + r;
            if (row >= M) continue;
            float* cp = &C[(size_t)row * NC + bn];
            int ri = rh*4 + r;
            if (!split) {
                *(float4*)&cp[(tx<<2)]      = *(float4*)&acc[ri][0];
                *(float4*)&cp[64+(tx<<2)]   = *(float4*)&acc[ri][4];
            } else {
#pragma unroll
                for (int c = 0; c < 4; c++) {
                    atomicAdd(&cp[(tx<<2)+c],    acc[ri][c]);
                    atomicAdd(&cp[64+(tx<<2)+c], acc[ri][4+c]);
                }
            }
        }
    }
}

// ---------------- small kernels ----------------
__global__ void k_filters(const float* __restrict__ lamb) {
    int i = blockIdx.x*256 + threadIdx.x;
    if (i >= NN) return;
    float lam = lamb[i];
    float l0 = 8.f*lam; if (l0 == 0.f) l0 = 1e-7f;
    float y0 = 2.f*PI_F*l0;
    g_filt[i] = sinf(y0)/y0;
    float l1 = lam*0.25f; if (l1 == 0.f) l1 = 1e-8f;
    g_filt[NN+i]   = sinf(l1)/(PI_F*l1)*(1.f-cosf(l1));
    float l2 = lam*0.5f;  if (l2 == 0.f) l2 = 1e-8f;
    g_filt[2*NN+i] = sinf(l2)/(PI_F*l2)*(1.f-cosf(l2));
}

__global__ void k_xw1(const float* __restrict__ x, const float* __restrict__ W1, const float* __restrict__ b1) {
    __shared__ float xr[8][128];
    int n0 = blockIdx.x * 8;
    int c = threadIdx.x;
#pragma unroll
    for (int i = 0; i < 8; i++) xr[i][c] = x[(size_t)(n0+i)*128 + c];
    __syncthreads();
    float acc[8];
#pragma unroll
    for (int i = 0; i < 8; i++) acc[i] = b1[c];
    for (int k = 0; k < 128; k++) {
        float w = W1[k*128 + c];
#pragma unroll
        for (int i = 0; i < 8; i++) acc[i] += xr[i][k]*w;
    }
#pragma unroll
    for (int i = 0; i < 8; i++) g_h[(size_t)(n0+i)*128 + c] = acc[i];
}

__global__ void k_scale3(const float* __restrict__ Cc, float* __restrict__ S, int w) {
    int i = blockIdx.x;
    float f0 = g_filt[i], f1 = g_filt[NN+i], f2 = g_filt[2*NN+i];
    const float* cr = &Cc[(size_t)i*w];
    float* sr = &S[(size_t)i*3*w];
    for (int j = threadIdx.x; j < w; j += blockDim.x) {
        float v = cr[j];
        sr[j] = f0*v; sr[w+j] = f1*v; sr[2*w+j] = f2*v;
    }
}

__global__ void k_scale1(const float* __restrict__ Cc, float* __restrict__ S, int w) {
    int i = blockIdx.x; float f0 = g_filt[i];
    for (int j = threadIdx.x; j < w; j += blockDim.x)
        S[(size_t)i*w+j] = f0*Cc[(size_t)i*w+j];
}

__global__ void k_absX2() {
    int i = blockIdx.x;
    for (int j = threadIdx.x; j < 256; j += blockDim.x)
        g_X2[(size_t)i*256+j] = fabsf(g_Y[(size_t)i*384 + 128 + j]);
}

__global__ void k_buildX3() {
    int i = blockIdx.x;
    const int zoff[4] = {256, 512, 384, 640}; // B1, B2, C1, C2 order
    for (int j = threadIdx.x; j < 512; j += blockDim.x)
        g_X3[(size_t)i*512+j] = fabsf(g_Z[(size_t)i*768 + zoff[j>>7] + (j&127)]);
}

__global__ void k_rep() {
    int i = blockIdx.x;
    for (int j = threadIdx.x; j < 896; j += blockDim.x) {
        float v;
        if (j < 128)      v = g_Y[(size_t)i*384 + j];          // A0
        else if (j < 384) v = g_Z[(size_t)i*768 + (j-128)];    // B0, C0
        else              v = g_Wo[(size_t)i*512 + (j-384)];   // D0 E0 F0 G0
        g_rep[(size_t)i*896 + j] = v;
    }
}

// ---------------- edge CSR ----------------
__global__ void k_deg() {
    int e = blockIdx.x*256 + threadIdx.x;
    if (e < EE) atomicAdd(&g_deg[g_dst[e]], 1);
}

__global__ void k_scan() {
    __shared__ int sh[1024];
    __shared__ int carry;
    int tid = threadIdx.x;
    if (tid == 0) carry = 0;
    __syncthreads();
    for (int base = 0; base < NN; base += 1024) {
        int idx = base + tid;
        int v = (idx < NN) ? g_deg[idx] : 0;
        sh[tid] = v;
        __syncthreads();
        for (int o = 1; o < 1024; o <<= 1) {
            int t = (tid >= o) ? sh[tid-o] : 0;
            __syncthreads();
            sh[tid] += t;
            __syncthreads();
        }
        if (idx < NN) g_off[idx] = carry + sh[tid] - v;
        __syncthreads();
        if (tid == 0) carry += sh[1023];
        __syncthreads();
    }
    if (tid == 0) g_off[NN] = carry;
}

__global__ void k_scatter() {
    int e = blockIdx.x*256 + threadIdx.x;
    if (e < EE) {
        int d = g_dst[e];
        int pos = atomicAdd(&g_cur[d], 1);
        g_esrc[pos] = g_src[e];
    }
}

// ---------------- aggregation / GAT / MLP ----------------
__global__ void __launch_bounds__(224) k_agg() {
    int d = blockIdx.x;
    int c = threadIdx.x; // 224 float4 lanes = 896 floats
    int s0 = g_off[d], s1 = g_off[d+1];
    const float4* rep4 = (const float4*)g_rep;
    float4 acc = make_float4(0.f,0.f,0.f,0.f);
    int i = s0;
    for (; i + 3 < s1; i += 4) {
        int sa = g_esrc[i], sb = g_esrc[i+1], sc = g_esrc[i+2], sd = g_esrc[i+3];
        float4 va = rep4[(size_t)sa*224 + c];
        float4 vb = rep4[(size_t)sb*224 + c];
        float4 vc = rep4[(size_t)sc*224 + c];
        float4 vd = rep4[(size_t)sd*224 + c];
        acc.x += (va.x+vb.x) + (vc.x+vd.x);
        acc.y += (va.y+vb.y) + (vc.y+vd.y);
        acc.z += (va.z+vb.z) + (vc.z+vd.z);
        acc.w += (va.w+vb.w) + (vc.w+vd.w);
    }
    for (; i < s1; i++) {
        int s = g_esrc[i];
        float4 v = rep4[(size_t)s*224 + c];
        acc.x += v.x; acc.y += v.y; acc.z += v.z; acc.w += v.w;
    }
    ((float4*)g_agg)[(size_t)d*224 + c] = acc;
}

__global__ void __launch_bounds__(256) k_hgat(const float* __restrict__ gatW) {
    __shared__ float ar[8][896];
    int n0 = blockIdx.x * 8;
    int tid = threadIdx.x;
    for (int idx = tid; idx < 8*896; idx += 256)
        ar[idx/896][idx%896] = g_agg[(size_t)(n0 + idx/896)*896 + (idx%896)];
    __syncthreads();
    int o = tid & 31, i = tid >> 5;
    float acc = 0.f;
    for (int k = 0; k < 896; k++) acc += ar[i][k] * gatW[k*32 + o];
    g_hgat[(size_t)(n0+i)*32 + o] = acc;
}

__global__ void k_attn(const float* __restrict__ attS, const float* __restrict__ attD) {
    int n = blockIdx.x*256 + threadIdx.x;
    if (n >= NN) return;
    float s0=0.f,s1=0.f,d0=0.f,d1=0.f;
#pragma unroll
    for (int c = 0; c < 16; c++) {
        float v0 = g_hgat[(size_t)n*32+c], v1 = g_hgat[(size_t)n*32+16+c];
        s0 += v0*attS[c];  s1 += v1*attS[16+c];
        d0 += v0*attD[c];  d1 += v1*attD[16+c];
    }
    g_asrc[2*n]=s0; g_asrc[2*n+1]=s1; g_adst[2*n]=d0; g_adst[2*n+1]=d1;
}

__device__ __forceinline__ float lrelu(float x){ return x > 0.f ? x : 0.2f*x; }

__global__ void __launch_bounds__(256) k_gat(const float* __restrict__ gatBias) {
    int d = blockIdx.x*8 + (threadIdx.x >> 5);
    int l = threadIdx.x & 31;
    int s0 = g_off[d], s1 = g_off[d+1];
    float ad0 = g_adst[2*d], ad1 = g_adst[2*d+1];
    float es0 = lrelu(g_asrc[2*d]   + ad0);
    float es1 = lrelu(g_asrc[2*d+1] + ad1);
    float m0 = (l==0) ? es0 : -INFINITY;
    float m1 = (l==0) ? es1 : -INFINITY;
    for (int i = s0 + l; i < s1; i += 32) {
        int s = g_esrc[i];
        m0 = fmaxf(m0, lrelu(g_asrc[2*s]   + ad0));
        m1 = fmaxf(m1, lrelu(g_asrc[2*s+1] + ad1));
    }
#pragma unroll
    for (int o = 16; o; o >>= 1) {
        m0 = fmaxf(m0, __shfl_xor_sync(0xffffffffu, m0, o));
        m1 = fmaxf(m1, __shfl_xor_sync(0xffffffffu, m1, o));
    }
    float z0 = (l==0) ? expf(es0 - m0) : 0.f;
    float z1 = (l==0) ? expf(es1 - m1) : 0.f;
    for (int i = s0 + l; i < s1; i += 32) {
        int s = g_esrc[i];
        z0 += expf(lrelu(g_asrc[2*s]   + ad0) - m0);
        z1 += expf(lrelu(g_asrc[2*s+1] + ad1) - m1);
    }
#pragma unroll
    for (int o = 16; o; o >>= 1) {
        z0 += __shfl_xor_sync(0xffffffffu, z0, o);
        z1 += __shfl_xor_sync(0xffffffffu, z1, o);
    }
    int hh = l >> 4;
    float mh  = hh ? m1 : m0;
    float inv = 1.f / (hh ? z1 : z0);
    float adh = hh ? ad1 : ad0;
    float acc = 0.f;
    for (int i = s0; i < s1; i++) {
        int s = g_esrc[i];
        float al = expf(lrelu(g_asrc[2*s+hh] + adh) - mh) * inv;
        acc += al * g_hgat[(size_t)s*32 + l];
    }
    {   // self loop
        float al = expf(lrelu(g_asrc[2*d+hh] + adh) - mh) * inv;
        acc += al * g_hgat[(size_t)d*32 + l];
    }
    g_gatout[(size_t)d*32 + l] = acc + gatBias[l];
}

__global__ void k_mlp(const float* __restrict__ mlpW, const float* __restrict__ mlpb) {
    int idx = blockIdx.x*256 + threadIdx.x;
    if (idx >= NN*16) return;
    int n = idx >> 4, c = idx & 15;
    float acc = mlpb[c];
#pragma unroll
    for (int o = 0; o < 32; o++) {
        float v = g_gatout[(size_t)n*32+o];
        v = v > 0.f ? v : (expf(v) - 1.f);
        acc += v * mlpW[o*16 + c];
    }
    g_gv[idx] = acc;
}

__global__ void k_out2() {
    int idx = blockIdx.x*256 + threadIdx.x;
    if (idx >= NN*16) return;
    int d = idx >> 4, c = idx & 15;
    int s0 = g_off[d], s1 = g_off[d+1];
    float acc = 0.f;
    for (int i = s0; i < s1; i++) acc += g_gv[(size_t)g_esrc[i]*16 + c];
    g_o2[idx] = acc;
}

__global__ void k_lsm(float* __restrict__ out) {
    int n = blockIdx.x*256 + threadIdx.x;
    if (n >= NN) return;
    float v[16]; float m = -INFINITY;
#pragma unroll
    for (int c = 0; c < 16; c++) { v[c] = g_o2[(size_t)n*16+c]; m = fmaxf(m, v[c]); }
    float z = 0.f;
#pragma unroll
    for (int c = 0; c < 16; c++) z += expf(v[c]-m);
    float lse = m + logf(z);
#pragma unroll
    for (int c = 0; c < 16; c++) out[(size_t)n*16+c] = v[c]-lse;
}

// ---------------- launcher ----------------
extern "C" void kernel_launch(void* const* d_in, const int* in_sizes, int n_in,
                              void* d_out, int out_size) {
    const float* x    = (const float*)d_in[0];
    const void*  ei   = d_in[1];                 // int32 or int64 — detected on device
    const float* lamb = (const float*)d_in[2];
    const float* V    = (const float*)d_in[3];
    const float* W1   = (const float*)d_in[4];
    const float* b1   = (const float*)d_in[5];
    const float* gatW = (const float*)d_in[6];
    const float* attS = (const float*)d_in[7];
    const float* attD = (const float*)d_in[8];
    const float* gatB = (const float*)d_in[9];
    const float* mlpW = (const float*)d_in[10];
    const float* mlpB = (const float*)d_in[11];
    float* out = (float*)d_out;

    float *h_, *C1_, *S1_, *Y_, *X2_, *C2_, *S2_, *Z_, *X3_, *C3_, *S3_, *Wo_;
    void *pDeg, *pOff, *pCur;
    cudaGetSymbolAddress((void**)&h_,  g_h);
    cudaGetSymbolAddress((void**)&C1_, g_C1);
    cudaGetSymbolAddress((void**)&S1_, g_S1);
    cudaGetSymbolAddress((void**)&Y_,  g_Y);
    cudaGetSymbolAddress((void**)&X2_, g_X2);
    cudaGetSymbolAddress((void**)&C2_, g_C2);
    cudaGetSymbolAddress((void**)&S2_, g_S2);
    cudaGetSymbolAddress((void**)&Z_,  g_Z);
    cudaGetSymbolAddress((void**)&X3_, g_X3);
    cudaGetSymbolAddress((void**)&C3_, g_C3);
    cudaGetSymbolAddress((void**)&S3_, g_S3);
    cudaGetSymbolAddress((void**)&Wo_, g_Wo);
    cudaGetSymbolAddress(&pDeg, g_deg);
    cudaGetSymbolAddress(&pOff, g_off);
    cudaGetSymbolAddress(&pCur, g_cur);

    // edge dtype detect + convert, then CSR
    k_detect<<<1,256>>>((const unsigned int*)ei);
    k_conv<<<CDIV(EE,256),256>>>(ei);
    cudaMemsetAsync(pDeg, 0, NN*sizeof(int));
    k_deg<<<CDIV(EE,256),256>>>();
    k_scan<<<1,1024>>>();
    cudaMemcpyAsync(pCur, pOff, NN*sizeof(int), cudaMemcpyDeviceToDevice);
    k_scatter<<<CDIV(EE,256),256>>>();

    // front end
    k_filters<<<CDIV(NN,256),256>>>(lamb);
    k_xw1<<<NN/8,128>>>(x, W1, b1);

    const int MT = CDIV(NN,128);   // 79
    const int KI = NN/8;           // 1250

    // G1: C1 = V^T h  (128 cols, split-K 4)
    cudaMemsetAsync(C1_, 0, (size_t)NN*128*sizeof(float));
    sgemm_k<true><<<dim3(MT,1,4),256>>>(V, h_, C1_, NN, NN, 128, CDIV(KI,4));
    k_scale3<<<NN,256>>>(C1_, S1_, 128);

    // G2: Y = V S1 (384 cols, split-K 2)
    cudaMemsetAsync(Y_, 0, (size_t)NN*384*sizeof(float));
    sgemm_k<false><<<dim3(MT,3,2),256>>>(V, S1_, Y_, NN, NN, 384, CDIV(KI,2));
    k_absX2<<<NN,256>>>();

    // G3: C2 = V^T X2 (256 cols, split-K 2)
    cudaMemsetAsync(C2_, 0, (size_t)NN*256*sizeof(float));
    sgemm_k<true><<<dim3(MT,2,2),256>>>(V, X2_, C2_, NN, NN, 256, CDIV(KI,2));
    k_scale3<<<NN,256>>>(C2_, S2_, 256);

    // G4: Z = V S2 (768 cols)
    sgemm_k<false><<<dim3(MT,6,1),256>>>(V, S2_, Z_, NN, NN, 768, KI);
    k_buildX3<<<NN,256>>>();

    // G5: C3 = V^T X3 (512 cols)
    sgemm_k<true><<<dim3(MT,4,1),256>>>(V, X3_, C3_, NN, NN, 512, KI);
    k_scale1<<<NN,256>>>(C3_, S3_, 512);

    // G6: Wo = V S3 (512 cols)
    sgemm_k<false><<<dim3(MT,4,1),256>>>(V, S3_, Wo_, NN, NN, 512, KI);
    k_rep<<<NN,256>>>();

    // graph aggregation + GAT + MLP + final agg + log_softmax
    k_agg<<<NN,224>>>();
    k_hgat<<<NN/8,256>>>(gatW);
    k_attn<<<CDIV(NN,256),256>>>(attS, attD);
    k_gat<<<NN/8,256>>>(gatB);
    k_mlp<<<CDIV(NN*16,256),256>>>(mlpW, mlpB);
    k_out2<<<CDIV(NN*16,256),256>>>();
    k_lsm<<<CDIV(NN,256),256>>>(out);
    (void)in_sizes; (void)n_in; (void)out_size;
}